// round 13
// baseline (speedup 1.0000x reference)
#include <cuda_runtime.h>
#include <math.h>
#include <limits.h>

#define NSIG 5
#define NROWS 10
#define SIG_LEN 2097152
#define HALF 5
#define THREADS 256
#define EPT 16
#define TILE (THREADS*EPT)        /* 4096 */
#define CHUNKS (SIG_LEN/TILE)     /* 512 */
#define HREC (CHUNKS*2)           /* 1024 half-chunk records per row */
#define RPT (HREC/THREADS)        /* 4 */
#define CAP 768                   /* >= 683 max peaks; multiple of 128 */
#define HCAP (CAP/2)              /* 384 entries per half-slice */
#define WPB 8                     /* half-chunks per pass2 block */
#define P2B (HREC/WPB)            /* 128 pass2 blocks per row */
#define NV 26                     /* v[0..25] = x[p0-5 .. p0+20] */
#define FULLM 0xFFFFFFFFu

struct __align__(16) ChunkRec { int first; int last; float inv; int pairs; };

__device__ float2 d_p1[NROWS*CHUNKS];              /* {sum, peak-sum} per chunk */
__device__ float d_thr[NROWS];
__device__ int2 d_pk[(size_t)NROWS*CHUNKS*CAP];
__device__ int d_cnt[NROWS*CHUNKS];
__device__ ChunkRec d_rec[NROWS*HREC];
__device__ double d_hr[NROWS];
__device__ int d_c1[NROWS];       /* zero-init; self-resetting */
__device__ int d_c2[NROWS];
__device__ int d_rows;

static __device__ __forceinline__ float neg_inf() { return __int_as_float(0xff800000); }

__device__ __forceinline__ const float* row_ptr(const float* rppg, const float* ppg, int s){
  return (s < NSIG) ? rppg + (size_t)s*SIG_LEN : ppg + (size_t)(s-NSIG)*SIG_LEN;
}

// v[5..20] = x[p0..p0+15]; halo v[0..4], v[21..25] via neighbor-lane shuffles.
__device__ __forceinline__ void load_vals(const float* __restrict__ x, int p0, float* v){
  #pragma unroll
  for (int q = 0; q < 4; q++) {
    float4 a = *reinterpret_cast<const float4*>(x + p0 + 4*q);
    v[5+4*q] = a.x; v[6+4*q] = a.y; v[7+4*q] = a.z; v[8+4*q] = a.w;
  }
  v[0]  = __shfl_up_sync(FULLM, v[16], 1);
  v[1]  = __shfl_up_sync(FULLM, v[17], 1);
  v[2]  = __shfl_up_sync(FULLM, v[18], 1);
  v[3]  = __shfl_up_sync(FULLM, v[19], 1);
  v[4]  = __shfl_up_sync(FULLM, v[20], 1);
  v[21] = __shfl_down_sync(FULLM, v[5], 1);
  v[22] = __shfl_down_sync(FULLM, v[6], 1);
  v[23] = __shfl_down_sync(FULLM, v[7], 1);
  v[24] = __shfl_down_sync(FULLM, v[8], 1);
  v[25] = __shfl_down_sync(FULLM, v[9], 1);
  int lane = threadIdx.x & 31;
  if (lane == 0) {
    #pragma unroll
    for (int k = 0; k < HALF; k++) {
      int g = p0 - HALF + k;
      v[k] = (g >= 0) ? __ldg(x + g) : neg_inf();
    }
  }
  if (lane == 31) {
    #pragma unroll
    for (int k = 0; k < HALF; k++) {
      int g = p0 + EPT + k;
      v[21+k] = (g < SIG_LEN) ? __ldg(x + g) : neg_inf();
    }
  }
}

// van Herk / Gil-Werman sliding max, width 11, 16 outputs, 47 fmax total.
// Local blocks: [0..10], [11..21], [22..25]. w[i] = max(S_block(i)[i], P_block(i+10)[i+10]).
__device__ __forceinline__ void window_max(const float* v, float* w){
  float S0[11];                       // S0[j] = max(v[j..10])
  S0[10] = v[10];
  #pragma unroll
  for (int j = 9; j >= 0; j--) S0[j] = fmaxf(v[j], S0[j+1]);
  float P1[11];                       // P1[j] = max(v[11..11+j])
  P1[0] = v[11];
  #pragma unroll
  for (int j = 1; j <= 10; j++) P1[j] = fmaxf(P1[j-1], v[11+j]);
  float S1[5];                        // S1[j] = max(v[11+j..21]), j=0..4
  {
    float r = v[21];
    #pragma unroll
    for (int j = 9; j >= 5; j--) r = fmaxf(v[11+j], r);
    S1[4] = fmaxf(v[15], r);
    S1[3] = fmaxf(v[14], S1[4]);
    S1[2] = fmaxf(v[13], S1[3]);
    S1[1] = fmaxf(v[12], S1[2]);
    S1[0] = fmaxf(v[11], S1[1]);
  }
  float P2[4];                        // P2[k] = max(v[22..22+k])
  P2[0] = v[22];
  P2[1] = fmaxf(P2[0], v[23]);
  P2[2] = fmaxf(P2[1], v[24]);
  P2[3] = fmaxf(P2[2], v[25]);
  w[0] = S0[0];                       // window [0..10] fully in block0
  #pragma unroll
  for (int i = 1; i <= 10; i++) w[i] = fmaxf(S0[i], P1[i-1]);   // [i..10] + [11..i+10]
  w[11] = S1[0];                      // window [11..21] fully in block1
  #pragma unroll
  for (int i = 12; i <= 15; i++) w[i] = fmaxf(S1[i-11], P2[i-12]); // [i..21] + [22..i+10]
}

// k1 = pass1 (stats + compact peak lists; 4 scalar slots per 16-span) +
//      last-block-per-row threshold.
__global__ void __launch_bounds__(THREADS) k1(const float* __restrict__ rppg,
                                              const float* __restrict__ ppg){
  int s = blockIdx.y;
  const float* __restrict__ x = row_ptr(rppg, ppg, s);
  int tid = threadIdx.x, lane = tid & 31, wid = tid >> 5;
  int p0 = blockIdx.x * TILE + tid * EPT;
  float v[NV]; load_vals(x, p0, v);
  float w[EPT]; window_max(v, w);
  float lsum = 0.f, lps = 0.f;
  int pa = -1, pb = -1, pc = -1, pd = -1;
  float va = 0.f, vb = 0.f, vc = 0.f, vd = 0.f;
  #pragma unroll
  for (int i = 0; i < EPT; i++) {
    float c = v[i + HALF];
    lsum += c;
    if (c == w[i]) {
      lps += c;
      if (pa < 0)      { pa = p0 + i; va = c; }
      else if (pb < 0) { pb = p0 + i; vb = c; }
      else if (pc < 0) { pc = p0 + i; vc = c; }
      else             { pd = p0 + i; vd = c; }
    }
  }
  int np = (pa >= 0) + (pb >= 0) + (pc >= 0) + (pd >= 0);
  // block-wide exclusive prefix of np
  int inc = np;
  #pragma unroll
  for (int off = 1; off < 32; off <<= 1) {
    int t = __shfl_up_sync(FULLM, inc, off);
    if (lane >= off) inc += t;
  }
  int exc = inc - np;
  __shared__ int wsum[8]; __shared__ int wbase[9];
  if (lane == 31) wsum[wid] = inc;
  __syncthreads();
  if (tid == 0) {
    int b = 0;
    #pragma unroll
    for (int ww = 0; ww < 8; ww++) { wbase[ww] = b; b += wsum[ww]; }
    wbase[8] = b;
  }
  __syncthreads();
  int base = wbase[wid] + exc;
  size_t cbase = (size_t)(s*CHUNKS + blockIdx.x) * CAP;
  if (pa >= 0) d_pk[cbase + base]     = make_int2(pa, __float_as_int(va));
  if (pb >= 0) d_pk[cbase + base + 1] = make_int2(pb, __float_as_int(vb));
  if (pc >= 0) d_pk[cbase + base + 2] = make_int2(pc, __float_as_int(vc));
  if (pd >= 0) d_pk[cbase + base + 3] = make_int2(pd, __float_as_int(vd));
  if (tid == 0) d_cnt[s*CHUNKS + blockIdx.x] = wbase[8];
  // stats reduction (sum, peak-sum)
  #pragma unroll
  for (int off = 16; off > 0; off >>= 1) {
    lsum += __shfl_down_sync(FULLM, lsum, off);
    lps  += __shfl_down_sync(FULLM, lps, off);
  }
  __shared__ float sA[8]; __shared__ float sB[8];
  if (lane == 0) { sA[wid] = lsum; sB[wid] = lps; }
  __syncthreads();
  if (tid == 0) {
    float a = 0.f, b = 0.f;
    #pragma unroll
    for (int ww = 0; ww < 8; ww++) { a += sA[ww]; b += sB[ww]; }
    d_p1[s*CHUNKS + blockIdx.x] = make_float2(a, b);
  }
  // all block writes complete BEFORE done-counter: barrier, then fence+atomic
  __syncthreads();
  __shared__ int amLast;
  if (tid == 0) {
    __threadfence();
    amLast = (atomicAdd(&d_c1[s], 1) == CHUNKS - 1);
  }
  __syncthreads();
  if (amLast) {
    double ls = 0.0, lpsd = 0.0; long long lcc = 0;
    for (int c = tid; c < CHUNKS; c += THREADS) {
      float2 r = d_p1[s*CHUNKS + c];
      ls += (double)r.x; lpsd += (double)r.y; lcc += d_cnt[s*CHUNKS + c];
    }
    #pragma unroll
    for (int off = 16; off > 0; off >>= 1) {
      ls   += __shfl_down_sync(FULLM, ls, off);
      lpsd += __shfl_down_sync(FULLM, lpsd, off);
      lcc  += __shfl_down_sync(FULLM, lcc, off);
    }
    __shared__ double tA[8]; __shared__ double tB[8]; __shared__ long long tC[8];
    if (lane == 0) { tA[wid] = ls; tB[wid] = lpsd; tC[wid] = lcc; }
    __syncthreads();
    if (tid == 0) {
      double a = 0.0, b = 0.0; long long c = 0;
      #pragma unroll
      for (int ww = 0; ww < 8; ww++) { a += tA[ww]; b += tB[ww]; c += tC[ww]; }
      double mu = a / (double)SIG_LEN;
      double mp = b / (double)c;
      d_thr[s] = (float)(0.5 * (mp + mu));
      d_c1[s] = 0;
    }
  }
}

// One 32-entry sub-batch: ballot+clz predecessor lookup, IEEE 1/g.
__device__ __forceinline__ void k2_process(int2 r, int e, int bound, float thr, int lane,
                                           float& linv, int& lpairs, int& lfirst, int& carry){
  int pos = (e < bound && __int_as_float(r.y) > thr) ? r.x : -1;
  unsigned mask = __ballot_sync(FULLM, pos >= 0);
  unsigned lower = mask & ((1u << lane) - 1u);
  int pl = 31 - __clz(lower);                     // -1 if no lower filtered lane
  int psrc = __shfl_sync(FULLM, pos, pl & 31);
  int prev = (pl >= 0) ? psrc : carry;
  if (pos >= 0) {
    if (prev >= 0) { linv += 1.0f / (float)(pos - prev); lpairs++; }
    lfirst = min(lfirst, pos);
  }
  int hl = 31 - __clz(mask);
  int hsrc = __shfl_sync(FULLM, pos, hl & 31);
  if (hl >= 0) carry = hsrc;                      // uniform across warp
}

// k2 = pass2: one warp per HALF-chunk (2x occupancy, half the serial carry
// chain vs one-warp-per-chunk). The generic record stitch bridges halves.
__global__ void __launch_bounds__(THREADS) k2(float* __restrict__ out){
  int s = blockIdx.y;
  int tid = threadIdx.x, lane = tid & 31, wid = tid >> 5;
  int h = blockIdx.x * WPB + wid;                 /* half-chunk id in [0, HREC) */
  int c = h >> 1, half = h & 1;
  int rowb2 = s * HREC;
  float thr = d_thr[s];
  int n = d_cnt[s*CHUNKS + c];
  int start = half * HCAP;
  int bound = half ? n : min(n, HCAP);            /* this warp's valid range [start, bound) */
  const int2* __restrict__ pk = d_pk + (size_t)(s*CHUNKS + c) * CAP;
  float linv = 0.f; int lpairs = 0; int lfirst = INT_MAX; int carry = -1;
  for (int base = start; base < bound; base += 128) {
    int e0 = base + lane, e1 = e0 + 32, e2 = e0 + 64, e3 = e0 + 96;
    int2 r0 = pk[e0];
    int2 r1 = pk[e1];
    int2 r2 = pk[e2];
    int2 r3 = pk[e3];
    k2_process(r0, e0, bound, thr, lane, linv, lpairs, lfirst, carry);
    k2_process(r1, e1, bound, thr, lane, linv, lpairs, lfirst, carry);
    k2_process(r2, e2, bound, thr, lane, linv, lpairs, lfirst, carry);
    k2_process(r3, e3, bound, thr, lane, linv, lpairs, lfirst, carry);
  }
  int blast = carry;
  #pragma unroll
  for (int off = 16; off > 0; off >>= 1) {
    linv   += __shfl_down_sync(FULLM, linv, off);
    lpairs += __shfl_down_sync(FULLM, lpairs, off);
    lfirst  = min(lfirst, __shfl_down_sync(FULLM, lfirst, off));
  }
  if (lane == 0) {
    ChunkRec r;
    r.first = (lfirst == INT_MAX) ? -1 : lfirst;
    r.last  = blast;
    r.inv   = linv;
    r.pairs = lpairs;
    d_rec[rowb2 + h] = r;
  }
  // every warp's d_rec write must land before the done-counter increment
  __syncthreads();
  __shared__ int amLast;
  if (tid == 0) {
    __threadfence();
    amLast = (atomicAdd(&d_c2[s], 1) == P2B - 1);
  }
  __syncthreads();
  if (amLast) {
    const int4* rec = reinterpret_cast<const int4*>(d_rec) + (size_t)rowb2 + (size_t)tid * RPT;
    double sinv = 0.0; int spairs = 0; int sfirst = -1, sprev = -1;
    #pragma unroll
    for (int r = 0; r < RPT; r++) {
      int4 rv = rec[r];
      if (rv.x >= 0) {
        if (sprev >= 0) { sinv += 1.0 / (double)(rv.x - sprev); spairs++; }
        else sfirst = rv.x;
        sprev = rv.y;
      }
      sinv += (double)__int_as_float(rv.z);
      spairs += rv.w;
    }
    int inc2 = sprev;
    #pragma unroll
    for (int off = 1; off < 32; off <<= 1) {
      int t = __shfl_up_sync(FULLM, inc2, off);
      if (lane >= off) inc2 = max(inc2, t);
    }
    int exw = __shfl_up_sync(FULLM, inc2, 1);
    if (lane == 0) exw = -1;
    __shared__ int wmax[8];
    if (lane == 31) wmax[wid] = inc2;
    __syncthreads();
    int wpre = -1;
    for (int ww = 0; ww < wid; ww++) wpre = max(wpre, wmax[ww]);
    int exprev2 = max(exw, wpre);
    if (sfirst >= 0 && exprev2 >= 0) { sinv += 1.0 / (double)(sfirst - exprev2); spairs++; }
    #pragma unroll
    for (int off = 16; off > 0; off >>= 1) {
      sinv   += __shfl_down_sync(FULLM, sinv, off);
      spairs += __shfl_down_sync(FULLM, spairs, off);
    }
    __shared__ double sD[8]; __shared__ int sP[8];
    if (lane == 0) { sD[wid] = sinv; sP[wid] = spairs; }
    __syncthreads();
    if (tid == 0) {
      double dsum = 0.0; int psum = 0;
      #pragma unroll
      for (int ww = 0; ww < 8; ww++) { dsum += sD[ww]; psum += sP[ww]; }
      d_hr[s] = dsum / (double)psum;
      d_c2[s] = 0;
      __threadfence();
      if (atomicAdd(&d_rows, 1) == NROWS - 1) {
        double acc = 0.0;
        #pragma unroll
        for (int i = 0; i < NSIG; i++) {
          double hp = d_hr[NSIG + i];
          double hq = d_hr[i];
          acc += fabs(hp - hq) / hp;
        }
        out[0] = (float)(acc / (double)NSIG);
        d_rows = 0;
      }
    }
  }
}

extern "C" void kernel_launch(void* const* d_in, const int* in_sizes, int n_in,
                              void* d_out, int out_size){
  (void)in_sizes; (void)n_in; (void)out_size;
  const float* rppg = (const float*)d_in[0];
  const float* ppg  = (const float*)d_in[1];
  float* out = (float*)d_out;
  dim3 g1(CHUNKS, NROWS);
  dim3 g2(P2B, NROWS);
  k1<<<g1, THREADS>>>(rppg, ppg);
  k2<<<g2, THREADS>>>(out);
}

// round 14
// speedup vs baseline: 1.0740x; 1.0740x over previous
#include <cuda_runtime.h>
#include <math.h>
#include <limits.h>

#define NSIG 5
#define NROWS 10
#define SIG_LEN 2097152
#define HALF 5
#define THREADS 256
#define EPT 16
#define TILE (THREADS*EPT)        /* 4096 */
#define CHUNKS (SIG_LEN/TILE)     /* 512 */
#define RPT (CHUNKS/THREADS)      /* 2 */
#define CAP 768                   /* >= 683 max peaks; multiple of 128 */
#define WPB 8                     /* chunks per pass2 block */
#define P2B (CHUNKS/WPB)          /* 64 pass2 blocks per row */
#define NV 26                     /* v[0..25] = x[p0-5 .. p0+20] */
#define FULLM 0xFFFFFFFFu

struct __align__(16) ChunkRec { int first; int last; float inv; int pairs; };

__device__ float2 d_p1[NROWS*CHUNKS];              /* {sum, peak-sum} per chunk */
__device__ float d_thr[NROWS];
__device__ int2 d_pk[(size_t)NROWS*CHUNKS*CAP];
__device__ int d_cnt[NROWS*CHUNKS];
__device__ ChunkRec d_rec[NROWS*CHUNKS];
__device__ double d_hr[NROWS];
__device__ int d_c1[NROWS];       /* zero-init; self-resetting */
__device__ int d_c2[NROWS];
__device__ int d_rows;

static __device__ __forceinline__ float neg_inf() { return __int_as_float(0xff800000); }

__device__ __forceinline__ const float* row_ptr(const float* rppg, const float* ppg, int s){
  return (s < NSIG) ? rppg + (size_t)s*SIG_LEN : ppg + (size_t)(s-NSIG)*SIG_LEN;
}

// v[5..20] = x[p0..p0+15]; halo v[0..4], v[21..25] via neighbor-lane shuffles.
__device__ __forceinline__ void load_vals(const float* __restrict__ x, int p0, float* v){
  #pragma unroll
  for (int q = 0; q < 4; q++) {
    float4 a = *reinterpret_cast<const float4*>(x + p0 + 4*q);
    v[5+4*q] = a.x; v[6+4*q] = a.y; v[7+4*q] = a.z; v[8+4*q] = a.w;
  }
  v[0]  = __shfl_up_sync(FULLM, v[16], 1);
  v[1]  = __shfl_up_sync(FULLM, v[17], 1);
  v[2]  = __shfl_up_sync(FULLM, v[18], 1);
  v[3]  = __shfl_up_sync(FULLM, v[19], 1);
  v[4]  = __shfl_up_sync(FULLM, v[20], 1);
  v[21] = __shfl_down_sync(FULLM, v[5], 1);
  v[22] = __shfl_down_sync(FULLM, v[6], 1);
  v[23] = __shfl_down_sync(FULLM, v[7], 1);
  v[24] = __shfl_down_sync(FULLM, v[8], 1);
  v[25] = __shfl_down_sync(FULLM, v[9], 1);
  int lane = threadIdx.x & 31;
  if (lane == 0) {
    #pragma unroll
    for (int k = 0; k < HALF; k++) {
      int g = p0 - HALF + k;
      v[k] = (g >= 0) ? __ldg(x + g) : neg_inf();
    }
  }
  if (lane == 31) {
    #pragma unroll
    for (int k = 0; k < HALF; k++) {
      int g = p0 + EPT + k;
      v[21+k] = (g < SIG_LEN) ? __ldg(x + g) : neg_inf();
    }
  }
}

// van Herk / Gil-Werman sliding max, width 11, 16 outputs, 47 fmax total.
__device__ __forceinline__ void window_max(const float* v, float* w){
  float S0[11];                       // S0[j] = max(v[j..10])
  S0[10] = v[10];
  #pragma unroll
  for (int j = 9; j >= 0; j--) S0[j] = fmaxf(v[j], S0[j+1]);
  float P1[11];                       // P1[j] = max(v[11..11+j])
  P1[0] = v[11];
  #pragma unroll
  for (int j = 1; j <= 10; j++) P1[j] = fmaxf(P1[j-1], v[11+j]);
  float S1[5];                        // S1[j] = max(v[11+j..21]), j=0..4
  {
    float r = v[21];
    #pragma unroll
    for (int j = 9; j >= 5; j--) r = fmaxf(v[11+j], r);
    S1[4] = fmaxf(v[15], r);
    S1[3] = fmaxf(v[14], S1[4]);
    S1[2] = fmaxf(v[13], S1[3]);
    S1[1] = fmaxf(v[12], S1[2]);
    S1[0] = fmaxf(v[11], S1[1]);
  }
  float P2[4];                        // P2[k] = max(v[22..22+k])
  P2[0] = v[22];
  P2[1] = fmaxf(P2[0], v[23]);
  P2[2] = fmaxf(P2[1], v[24]);
  P2[3] = fmaxf(P2[2], v[25]);
  w[0] = S0[0];
  #pragma unroll
  for (int i = 1; i <= 10; i++) w[i] = fmaxf(S0[i], P1[i-1]);
  w[11] = S1[0];
  #pragma unroll
  for (int i = 12; i <= 15; i++) w[i] = fmaxf(S1[i-11], P2[i-12]);
}

// k1 = pass1 (stats + compact peak lists; 4 scalar slots per 16-span) +
//      last-block-per-row threshold. Register-capped for >=4 blocks/SM (MLP).
__global__ void __launch_bounds__(THREADS, 4) k1(const float* __restrict__ rppg,
                                                 const float* __restrict__ ppg){
  int s = blockIdx.y;
  const float* __restrict__ x = row_ptr(rppg, ppg, s);
  int tid = threadIdx.x, lane = tid & 31, wid = tid >> 5;
  int p0 = blockIdx.x * TILE + tid * EPT;
  float v[NV]; load_vals(x, p0, v);
  float w[EPT]; window_max(v, w);
  float lsum = 0.f, lps = 0.f;
  int pa = -1, pb = -1, pc = -1, pd = -1;
  float va = 0.f, vb = 0.f, vc = 0.f, vd = 0.f;
  #pragma unroll
  for (int i = 0; i < EPT; i++) {
    float c = v[i + HALF];
    lsum += c;
    if (c == w[i]) {
      lps += c;
      if (pa < 0)      { pa = p0 + i; va = c; }
      else if (pb < 0) { pb = p0 + i; vb = c; }
      else if (pc < 0) { pc = p0 + i; vc = c; }
      else             { pd = p0 + i; vd = c; }
    }
  }
  int np = (pa >= 0) + (pb >= 0) + (pc >= 0) + (pd >= 0);
  // block-wide exclusive prefix of np
  int inc = np;
  #pragma unroll
  for (int off = 1; off < 32; off <<= 1) {
    int t = __shfl_up_sync(FULLM, inc, off);
    if (lane >= off) inc += t;
  }
  int exc = inc - np;
  __shared__ int wsum[8]; __shared__ int wbase[9];
  if (lane == 31) wsum[wid] = inc;
  __syncthreads();
  if (tid == 0) {
    int b = 0;
    #pragma unroll
    for (int ww = 0; ww < 8; ww++) { wbase[ww] = b; b += wsum[ww]; }
    wbase[8] = b;
  }
  __syncthreads();
  int base = wbase[wid] + exc;
  size_t cbase = (size_t)(s*CHUNKS + blockIdx.x) * CAP;
  if (pa >= 0) d_pk[cbase + base]     = make_int2(pa, __float_as_int(va));
  if (pb >= 0) d_pk[cbase + base + 1] = make_int2(pb, __float_as_int(vb));
  if (pc >= 0) d_pk[cbase + base + 2] = make_int2(pc, __float_as_int(vc));
  if (pd >= 0) d_pk[cbase + base + 3] = make_int2(pd, __float_as_int(vd));
  if (tid == 0) d_cnt[s*CHUNKS + blockIdx.x] = wbase[8];
  // stats reduction (sum, peak-sum)
  #pragma unroll
  for (int off = 16; off > 0; off >>= 1) {
    lsum += __shfl_down_sync(FULLM, lsum, off);
    lps  += __shfl_down_sync(FULLM, lps, off);
  }
  __shared__ float sA[8]; __shared__ float sB[8];
  if (lane == 0) { sA[wid] = lsum; sB[wid] = lps; }
  __syncthreads();
  if (tid == 0) {
    float a = 0.f, b = 0.f;
    #pragma unroll
    for (int ww = 0; ww < 8; ww++) { a += sA[ww]; b += sB[ww]; }
    d_p1[s*CHUNKS + blockIdx.x] = make_float2(a, b);
  }
  // all block writes complete BEFORE done-counter: barrier, then fence+atomic
  __syncthreads();
  __shared__ int amLast;
  if (tid == 0) {
    __threadfence();
    amLast = (atomicAdd(&d_c1[s], 1) == CHUNKS - 1);
  }
  __syncthreads();
  if (amLast) {
    double ls = 0.0, lpsd = 0.0; long long lcc = 0;
    for (int c = tid; c < CHUNKS; c += THREADS) {
      float2 r = d_p1[s*CHUNKS + c];
      ls += (double)r.x; lpsd += (double)r.y; lcc += d_cnt[s*CHUNKS + c];
    }
    #pragma unroll
    for (int off = 16; off > 0; off >>= 1) {
      ls   += __shfl_down_sync(FULLM, ls, off);
      lpsd += __shfl_down_sync(FULLM, lpsd, off);
      lcc  += __shfl_down_sync(FULLM, lcc, off);
    }
    __shared__ double tA[8]; __shared__ double tB[8]; __shared__ long long tC[8];
    if (lane == 0) { tA[wid] = ls; tB[wid] = lpsd; tC[wid] = lcc; }
    __syncthreads();
    if (tid == 0) {
      double a = 0.0, b = 0.0; long long c = 0;
      #pragma unroll
      for (int ww = 0; ww < 8; ww++) { a += tA[ww]; b += tB[ww]; c += tC[ww]; }
      double mu = a / (double)SIG_LEN;
      double mp = b / (double)c;
      d_thr[s] = (float)(0.5 * (mp + mu));
      d_c1[s] = 0;
    }
  }
}

// One 32-entry sub-batch: ballot+clz predecessor lookup, IEEE 1/g.
__device__ __forceinline__ void k2_process(int2 r, int e, int n, float thr, int lane,
                                           float& linv, int& lpairs, int& lfirst, int& carry){
  int pos = (e < n && __int_as_float(r.y) > thr) ? r.x : -1;
  unsigned mask = __ballot_sync(FULLM, pos >= 0);
  unsigned lower = mask & ((1u << lane) - 1u);
  int pl = 31 - __clz(lower);                     // -1 if no lower filtered lane
  int psrc = __shfl_sync(FULLM, pos, pl & 31);
  int prev = (pl >= 0) ? psrc : carry;
  if (pos >= 0) {
    if (prev >= 0) { linv += 1.0f / (float)(pos - prev); lpairs++; }
    lfirst = min(lfirst, pos);
  }
  int hl = 31 - __clz(mask);
  int hsrc = __shfl_sync(FULLM, pos, hl & 31);
  if (hl >= 0) carry = hsrc;                      // uniform across warp
}

// k2 = pass2 with 4-deep load pipelining (round-10 version: best measured).
__global__ void __launch_bounds__(THREADS) k2(float* __restrict__ out){
  int s = blockIdx.y;
  int tid = threadIdx.x, lane = tid & 31, wid = tid >> 5;
  int c = blockIdx.x * WPB + wid;
  int rowb = s * CHUNKS;
  float thr = d_thr[s];
  int n = d_cnt[rowb + c];
  const int2* __restrict__ pk = d_pk + (size_t)(rowb + c) * CAP;
  float linv = 0.f; int lpairs = 0; int lfirst = INT_MAX; int carry = -1;
  for (int base = 0; base < n; base += 128) {
    int e0 = base + lane, e1 = e0 + 32, e2 = e0 + 64, e3 = e0 + 96;
    int2 r0 = pk[e0];
    int2 r1 = pk[e1];
    int2 r2 = pk[e2];
    int2 r3 = pk[e3];
    k2_process(r0, e0, n, thr, lane, linv, lpairs, lfirst, carry);
    k2_process(r1, e1, n, thr, lane, linv, lpairs, lfirst, carry);
    k2_process(r2, e2, n, thr, lane, linv, lpairs, lfirst, carry);
    k2_process(r3, e3, n, thr, lane, linv, lpairs, lfirst, carry);
  }
  int blast = carry;
  #pragma unroll
  for (int off = 16; off > 0; off >>= 1) {
    linv   += __shfl_down_sync(FULLM, linv, off);
    lpairs += __shfl_down_sync(FULLM, lpairs, off);
    lfirst  = min(lfirst, __shfl_down_sync(FULLM, lfirst, off));
  }
  if (lane == 0) {
    ChunkRec r;
    r.first = (lfirst == INT_MAX) ? -1 : lfirst;
    r.last  = blast;
    r.inv   = linv;
    r.pairs = lpairs;
    d_rec[rowb + c] = r;
  }
  // every warp's d_rec write must land before the done-counter increment
  __syncthreads();
  __shared__ int amLast;
  if (tid == 0) {
    __threadfence();
    amLast = (atomicAdd(&d_c2[s], 1) == P2B - 1);
  }
  __syncthreads();
  if (amLast) {
    const int4* rec = reinterpret_cast<const int4*>(d_rec) + (size_t)rowb + (size_t)tid * RPT;
    double sinv = 0.0; int spairs = 0; int sfirst = -1, sprev = -1;
    #pragma unroll
    for (int r = 0; r < RPT; r++) {
      int4 rv = rec[r];
      if (rv.x >= 0) {
        if (sprev >= 0) { sinv += 1.0 / (double)(rv.x - sprev); spairs++; }
        else sfirst = rv.x;
        sprev = rv.y;
      }
      sinv += (double)__int_as_float(rv.z);
      spairs += rv.w;
    }
    int inc2 = sprev;
    #pragma unroll
    for (int off = 1; off < 32; off <<= 1) {
      int t = __shfl_up_sync(FULLM, inc2, off);
      if (lane >= off) inc2 = max(inc2, t);
    }
    int exw = __shfl_up_sync(FULLM, inc2, 1);
    if (lane == 0) exw = -1;
    __shared__ int wmax[8];
    if (lane == 31) wmax[wid] = inc2;
    __syncthreads();
    int wpre = -1;
    for (int ww = 0; ww < wid; ww++) wpre = max(wpre, wmax[ww]);
    int exprev2 = max(exw, wpre);
    if (sfirst >= 0 && exprev2 >= 0) { sinv += 1.0 / (double)(sfirst - exprev2); spairs++; }
    #pragma unroll
    for (int off = 16; off > 0; off >>= 1) {
      sinv   += __shfl_down_sync(FULLM, sinv, off);
      spairs += __shfl_down_sync(FULLM, spairs, off);
    }
    __shared__ double sD[8]; __shared__ int sP[8];
    if (lane == 0) { sD[wid] = sinv; sP[wid] = spairs; }
    __syncthreads();
    if (tid == 0) {
      double dsum = 0.0; int psum = 0;
      #pragma unroll
      for (int ww = 0; ww < 8; ww++) { dsum += sD[ww]; psum += sP[ww]; }
      d_hr[s] = dsum / (double)psum;
      d_c2[s] = 0;
      __threadfence();
      if (atomicAdd(&d_rows, 1) == NROWS - 1) {
        double acc = 0.0;
        #pragma unroll
        for (int i = 0; i < NSIG; i++) {
          double hp = d_hr[NSIG + i];
          double hq = d_hr[i];
          acc += fabs(hp - hq) / hp;
        }
        out[0] = (float)(acc / (double)NSIG);
        d_rows = 0;
      }
    }
  }
}

extern "C" void kernel_launch(void* const* d_in, const int* in_sizes, int n_in,
                              void* d_out, int out_size){
  (void)in_sizes; (void)n_in; (void)out_size;
  const float* rppg = (const float*)d_in[0];
  const float* ppg  = (const float*)d_in[1];
  float* out = (float*)d_out;
  dim3 g1(CHUNKS, NROWS);
  dim3 g2(P2B, NROWS);
  k1<<<g1, THREADS>>>(rppg, ppg);
  k2<<<g2, THREADS>>>(out);
}